// round 2
// baseline (speedup 1.0000x reference)
#include <cuda_runtime.h>

// ---------------------------------------------------------------------------
// MaskedBalancedBCELoss — single-pass persistent fused kernel.
//
// Selection: neg loss -log1p(-p) is monotone in p, so top-k negatives by loss
// == top-k by pred. Phase A builds a 32-bin histogram of p over negatives and
// stashes candidate preds (bin >= 16) in SMEM. After a device-wide software
// barrier, Phase B resolves the threshold bin from SMEM candidates (64
// sub-bins in the crossing bin, mean-interpolated partial sub-bin). Fallback
// (threshold below the static cut, or buffer overflow): the affected block
// re-reads its own global range. Block 0 finalizes + resets globals so the
// kernel is CUDA-graph-replay safe.
// ---------------------------------------------------------------------------

#define NB1 32
#define NB2 64
#define BLK 512
#define GRID_MAX 148
#define CUT_BIN 16
#define CAP 44032   // candidate floats per block (expected ~37.3k)

__device__ unsigned int g_h1[NB1];
__device__ unsigned int g_h2c[NB2];
__device__ float        g_h2s[NB2];
__device__ unsigned int g_pos_cnt;
__device__ double       g_pos_sum;
__device__ double       g_above_sum;
__device__ volatile unsigned int g_bar1;
__device__ volatile unsigned int g_bar2;

__device__ __forceinline__ float pos_loss(float p) { return fminf(-__logf(p), 100.0f); }
__device__ __forceinline__ float neg_loss(float p) { return fminf(-__logf(1.0f - p), 100.0f); }

extern __shared__ unsigned char dynsmem[];

__global__ void __launch_bounds__(BLK, 1) fused_bce(
    const float4* __restrict__ pred4, const float4* __restrict__ gt4,
    const float4* __restrict__ mask4,
    const float* __restrict__ pred, const float* __restrict__ gt,
    const float* __restrict__ mask, int n, float* __restrict__ out)
{
    float*        buf  = (float*)dynsmem;                         // CAP floats
    unsigned int* hist = (unsigned int*)(dynsmem + CAP * 4);      // 8*BLK words (u8 packed x4 bins)

    __shared__ unsigned int s_binsum[NB1];
    __shared__ unsigned int s_c2[NB2];
    __shared__ float        s_s2[NB2];
    __shared__ unsigned int s_cnt;
    __shared__ int          s_over;
    __shared__ int          s_T1;
    __shared__ unsigned int s_h1[NB1];
    __shared__ unsigned int w_pc[BLK / 32];
    __shared__ float        w_ps[BLK / 32];
    __shared__ float        w_as[BLK / 32];

    const int tid  = threadIdx.x;
    const int lane = tid & 31;

#pragma unroll
    for (int w = 0; w < 8; w++) hist[w * BLK + tid] = 0u;
    if (tid < NB1) s_binsum[tid] = 0u;
    if (tid < NB2) { s_c2[tid] = 0u; s_s2[tid] = 0.0f; }
    if (tid == 0) { s_cnt = 0u; s_over = 0; }
    __syncthreads();

    unsigned int posc = 0;
    float poss = 0.0f;
    const int n4   = n >> 2;
    const int step = gridDim.x * BLK;

    // Warp-aggregated candidate append. Must be called with full-warp convergence.
    auto appendWarp = [&](bool cand, float p) {
        unsigned m = __ballot_sync(0xffffffffu, cand);
        if (m) {
            int leader = __ffs(m) - 1;
            unsigned base = 0;
            if (lane == leader) base = atomicAdd(&s_cnt, (unsigned)__popc(m));
            base = __shfl_sync(0xffffffffu, base, leader);
            if (cand) {
                unsigned off = base + (unsigned)__popc(m & ((1u << lane) - 1u));
                if (off < CAP) buf[off] = p; else s_over = 1;
            }
        }
    };

    auto procA = [&](float p, float g, float mm, bool in) {
        bool valid = in && (mm > 0.5f);
        bool ispos = valid && (g > 0.5f);
        bool isneg = valid && !(g > 0.5f);
        int b = (int)(p * 32.0f);
        b = max(0, min(b, NB1 - 1));
        if (ispos) { posc++; poss += pos_loss(p); }
        if (isneg) hist[(b >> 2) * BLK + tid] += (1u << ((b & 3) * 8));
        appendWarp(isneg && (b >= CUT_BIN), p);
    };

    // ---- Phase A: the single DRAM pass (unroll x3 for MLP) -----------------
    int ibase = blockIdx.x * BLK;
    const int bigstep = 3 * step;
    for (; ibase + 2 * step + BLK <= n4; ibase += bigstep) {
        int i0 = ibase + tid, i1 = i0 + step, i2 = i1 + step;
        float4 pa = pred4[i0], pb = pred4[i1], pc = pred4[i2];
        float4 ga = gt4[i0],   gb = gt4[i1],   gc = gt4[i2];
        float4 ma = mask4[i0], mb = mask4[i1], mc = mask4[i2];
        procA(pa.x, ga.x, ma.x, true); procA(pa.y, ga.y, ma.y, true);
        procA(pa.z, ga.z, ma.z, true); procA(pa.w, ga.w, ma.w, true);
        procA(pb.x, gb.x, mb.x, true); procA(pb.y, gb.y, mb.y, true);
        procA(pb.z, gb.z, mb.z, true); procA(pb.w, gb.w, mb.w, true);
        procA(pc.x, gc.x, mc.x, true); procA(pc.y, gc.y, mc.y, true);
        procA(pc.z, gc.z, mc.z, true); procA(pc.w, gc.w, mc.w, true);
    }
    // remainder: block-uniform trip count, predicated loads (ballot stays legal)
    for (; ibase < n4; ibase += step) {
        int i = ibase + tid;
        bool in = i < n4;
        float4 p = in ? pred4[i] : make_float4(0.f, 0.f, 0.f, 0.f);
        float4 g = in ? gt4[i]   : make_float4(1.f, 1.f, 1.f, 1.f);
        float4 m = in ? mask4[i] : make_float4(0.f, 0.f, 0.f, 0.f);
        procA(p.x, g.x, m.x, in); procA(p.y, g.y, m.y, in);
        procA(p.z, g.z, m.z, in); procA(p.w, g.w, m.w, in);
    }
    // scalar tail (n % 4), block 0 only, per-thread append (no ballot)
    if (blockIdx.x == 0) {
        for (int i = (n4 << 2) + tid; i < n; i += BLK) {
            float p = pred[i], g = gt[i], mm = mask[i];
            bool valid = mm > 0.5f;
            bool ispos = valid && (g > 0.5f);
            bool isneg = valid && !(g > 0.5f);
            int b = (int)(p * 32.0f);
            b = max(0, min(b, NB1 - 1));
            if (ispos) { posc++; poss += pos_loss(p); }
            if (isneg) {
                hist[(b >> 2) * BLK + tid] += (1u << ((b & 3) * 8));
                if (b >= CUT_BIN) {
                    unsigned off = atomicAdd(&s_cnt, 1u);
                    if (off < CAP) buf[off] = p; else s_over = 1;
                }
            }
        }
    }
    __syncthreads();

    // flush per-thread u8 histograms (conflict-free staggered columns)
    {
        const int b     = tid & 31;
        const int chunk = tid >> 5;                 // 16 chunks of 32 threads
        const int w     = (b >> 2) * BLK;
        const int sh    = (b & 3) * 8;
        unsigned s = 0;
#pragma unroll
        for (int jj = 0; jj < 32; jj++) {
            int j = chunk * 32 + ((jj + b) & 31);
            s += (hist[w + j] >> sh) & 0xFFu;
        }
        if (s) atomicAdd(&s_binsum[b], s);
    }

    // positive stats reduction
#pragma unroll
    for (int o = 16; o > 0; o >>= 1) {
        posc += __shfl_down_sync(0xffffffffu, posc, o);
        poss += __shfl_down_sync(0xffffffffu, poss, o);
    }
    if (lane == 0) { w_pc[tid >> 5] = posc; w_ps[tid >> 5] = poss; }
    __syncthreads();

    if (tid < NB1 && s_binsum[tid]) atomicAdd(&g_h1[tid], s_binsum[tid]);
    if (tid == 0) {
        unsigned pc = 0; float ps = 0.0f;
#pragma unroll
        for (int w = 0; w < BLK / 32; w++) { pc += w_pc[w]; ps += w_ps[w]; }
        if (pc) atomicAdd(&g_pos_cnt, pc);
        atomicAdd(&g_pos_sum, (double)ps);
    }

    // ---- global barrier 1 --------------------------------------------------
    __threadfence();
    __syncthreads();
    if (tid == 0) {
        atomicAdd(const_cast<unsigned int*>(&g_bar1), 1u);
        while (g_bar1 < gridDim.x) __nanosleep(32);
        __threadfence();
    }
    __syncthreads();

    // ---- Phase B: resolve threshold from SMEM candidates -------------------
    if (tid < NB1) s_h1[tid] = g_h1[tid];
    __syncthreads();
    if (tid == 0) {
        long long negtot = 0;
        for (int i = 0; i < NB1; i++) negtot += (long long)s_h1[i];
        unsigned pos = g_pos_cnt;
        long long k3p = 3LL * (long long)pos;
        long long k = (pos == 0u) ? 0LL : (negtot < k3p ? negtot : k3p);
        int T1 = 1000;
        if (k > 0) {
            long long c = 0;
            for (int i = NB1 - 1; i >= 0; i--) {
                c += (long long)s_h1[i];
                if (c >= k) { T1 = i; break; }
            }
        }
        s_T1 = T1;
    }
    __syncthreads();
    const int T1 = s_T1;

    float asum = 0.0f;
    if (T1 < NB1) {  // k > 0
        bool fast = (T1 >= CUT_BIN) && (s_over == 0) && (s_cnt <= CAP);
        if (fast) {
            const unsigned cnt = s_cnt;
            for (unsigned j = tid; j < cnt; j += BLK) {
                float p = buf[j];
                int b = (int)(p * 32.0f);
                b = max(0, min(b, NB1 - 1));
                if (b > T1) {
                    asum += neg_loss(p);
                } else if (b == T1) {
                    int b2 = (int)(p * 2048.0f) - T1 * 64;
                    b2 = max(0, min(b2, NB2 - 1));
                    atomicAdd(&s_c2[b2], 1u);
                    atomicAdd(&s_s2[b2], neg_loss(p));
                }
            }
        } else {
            // fallback: re-read this block's own global range
            for (int ib = blockIdx.x * BLK; ib < n4; ib += step) {
                int i = ib + tid;
                if (i < n4) {
                    float4 p = pred4[i], g = gt4[i], m = mask4[i];
                    float ps_[4] = {p.x, p.y, p.z, p.w};
                    float gs_[4] = {g.x, g.y, g.z, g.w};
                    float ms_[4] = {m.x, m.y, m.z, m.w};
#pragma unroll
                    for (int c = 0; c < 4; c++) {
                        if (ms_[c] > 0.5f && gs_[c] < 0.5f) {
                            int b = (int)(ps_[c] * 32.0f);
                            b = max(0, min(b, NB1 - 1));
                            if (b > T1) asum += neg_loss(ps_[c]);
                            else if (b == T1) {
                                int b2 = (int)(ps_[c] * 2048.0f) - T1 * 64;
                                b2 = max(0, min(b2, NB2 - 1));
                                atomicAdd(&s_c2[b2], 1u);
                                atomicAdd(&s_s2[b2], neg_loss(ps_[c]));
                            }
                        }
                    }
                }
            }
            if (blockIdx.x == 0) {
                for (int i = (n4 << 2) + tid; i < n; i += BLK) {
                    float p = pred[i], g = gt[i], mm = mask[i];
                    if (mm > 0.5f && g < 0.5f) {
                        int b = (int)(p * 32.0f);
                        b = max(0, min(b, NB1 - 1));
                        if (b > T1) asum += neg_loss(p);
                        else if (b == T1) {
                            int b2 = (int)(p * 2048.0f) - T1 * 64;
                            b2 = max(0, min(b2, NB2 - 1));
                            atomicAdd(&s_c2[b2], 1u);
                            atomicAdd(&s_s2[b2], neg_loss(p));
                        }
                    }
                }
            }
        }
    }

#pragma unroll
    for (int o = 16; o > 0; o >>= 1)
        asum += __shfl_down_sync(0xffffffffu, asum, o);
    if (lane == 0) w_as[tid >> 5] = asum;
    __syncthreads();

    if (tid < NB2 && s_c2[tid]) {
        atomicAdd(&g_h2c[tid], s_c2[tid]);
        atomicAdd(&g_h2s[tid], s_s2[tid]);
    }
    if (tid == 0) {
        float as = 0.0f;
#pragma unroll
        for (int w = 0; w < BLK / 32; w++) as += w_as[w];
        atomicAdd(&g_above_sum, (double)as);
    }

    // ---- global barrier 2: arrive; only block 0 continues ------------------
    __threadfence();
    __syncthreads();
    if (tid == 0) atomicAdd(const_cast<unsigned int*>(&g_bar2), 1u);
    if (blockIdx.x != 0) return;

    if (tid == 0) {
        while (g_bar2 < gridDim.x) __nanosleep(32);
        __threadfence();
    }
    __syncthreads();

    // ---- finalize (block 0) -------------------------------------------------
    if (tid == 0) {
        long long negtot = 0;
        for (int i = 0; i < NB1; i++) negtot += (long long)g_h1[i];
        unsigned pos = g_pos_cnt;
        long long k3p = 3LL * (long long)pos;
        long long k = (pos == 0u) ? 0LL : (negtot < k3p ? negtot : k3p);

        double nsum = 0.0;
        if (k > 0) {
            long long c = 0, cAbove1 = 0;
            for (int i = NB1 - 1; i >= 0; i--) {
                long long cn = c + (long long)g_h1[i];
                if (cn >= k) { cAbove1 = c; break; }
                c = cn;
            }
            long long r = k - cAbove1;   // take r from bin T1 (r >= 1)

            long long c2 = 0, cAbove2 = 0;
            double s2above = 0.0;
            int T2 = -1;
            for (int i = NB2 - 1; i >= 0; i--) {
                long long cn = c2 + (long long)g_h2c[i];
                if (cn >= r) { T2 = i; cAbove2 = c2; break; }
                s2above += (double)g_h2s[i];
                c2 = cn;
            }
            double part = 0.0;
            if (T2 >= 0 && g_h2c[T2] > 0u) {
                long long r2 = r - cAbove2;
                if (r2 < 0) r2 = 0;
                part = (double)g_h2s[T2] * ((double)r2 / (double)g_h2c[T2]);
            }
            nsum = g_above_sum + s2above + part;
        }

        double denom = (double)pos + (double)k + 1e-6;
        out[0] = (float)((g_pos_sum + nsum) / denom);
    }
    __syncthreads();   // all finalize reads done before reset

    // reset globals for graph replay
    if (tid < NB1) g_h1[tid] = 0u;
    if (tid < NB2) { g_h2c[tid] = 0u; g_h2s[tid] = 0.0f; }
    if (tid == 0) {
        g_pos_cnt   = 0u;
        g_pos_sum   = 0.0;
        g_above_sum = 0.0;
        g_bar1 = 0u;
        g_bar2 = 0u;
    }
}

// ---------------------------------------------------------------------------
extern "C" void kernel_launch(void* const* d_in, const int* in_sizes, int n_in,
                              void* d_out, int out_size)
{
    const float* pred = (const float*)d_in[0];
    const float* gt   = (const float*)d_in[1];
    const float* mask = (const float*)d_in[2];
    float* out = (float*)d_out;
    const int n = in_sizes[0];

    const float4* pred4 = (const float4*)pred;
    const float4* gt4   = (const float4*)gt;
    const float4* mask4 = (const float4*)mask;

    int n4 = n >> 2;
    int grid = (n4 + BLK - 1) / BLK;
    if (grid > GRID_MAX) grid = GRID_MAX;
    if (grid < 1) grid = 1;

    const size_t shmem = (size_t)CAP * 4 + 8 * BLK * 4;  // ~192.5 KB
    cudaFuncSetAttribute(fused_bce, cudaFuncAttributeMaxDynamicSharedMemorySize,
                         (int)shmem);
    fused_bce<<<grid, BLK, shmem>>>(pred4, gt4, mask4, pred, gt, mask, n, out);
}

// round 3
// speedup vs baseline: 1.5613x; 1.5613x over previous
#include <cuda_runtime.h>

// ---------------------------------------------------------------------------
// MaskedBalancedBCELoss — 3-kernel pipeline with candidate compaction.
//
//  K1: single full read (157 MB). Per-thread u8-packed 32-bin histogram of p
//      over negatives (conflict-free, no atomics), positive count/sum, and
//      warp-aggregated compaction of candidate preds (negatives with p>=0.5)
//      into a per-block region of a global scratch array (~22 MB written).
//  K2: resolves threshold bin T1 from the 32-bin histogram; re-reads ONLY the
//      compacted candidates (22 MB): exact loss sum for bins > T1, 64-sub-bin
//      count/sum histogram inside bin T1. Fallback to full re-read if T1 < 16
//      or scratch was disabled (never on this data; keeps correctness
//      unconditional).
//  K3: resolves the sub-bin crossing (mean-interpolated partial sub-bin),
//      writes the scalar, resets all globals (graph-replay safe).
// ---------------------------------------------------------------------------

#define NB1 32
#define NB2 64
#define BLK 256
#define GRID_CAP 888           // 148 SMs * 6
#define SCR_SZ (16u << 20)     // 16M floats = 64 MB scratch

__device__ float        g_scr[SCR_SZ];
__device__ unsigned int g_cnt_blk[GRID_CAP];
__device__ unsigned int g_h1[NB1];
__device__ unsigned int g_h2c[NB2];
__device__ float        g_h2s[NB2];
__device__ unsigned int g_pos_cnt;
__device__ double       g_pos_sum;
__device__ double       g_above_sum;

__device__ __forceinline__ float pos_loss(float p) { return fminf(-__logf(p), 100.0f); }
__device__ __forceinline__ float neg_loss(float p) { return fminf(-__logf(1.0f - p), 100.0f); }

// ---------------------------------------------------------------------------
// K1
// ---------------------------------------------------------------------------
__global__ void __launch_bounds__(BLK) k1_hist(
    const float4* __restrict__ pred4, const float4* __restrict__ gt4,
    const float4* __restrict__ mask4,
    const float* __restrict__ pred, const float* __restrict__ gt,
    const float* __restrict__ mask, int n, int cap, int use_scr)
{
    __shared__ unsigned int sh[8 * BLK];       // u8-packed: word w holds bins 4w..4w+3
    __shared__ unsigned int s_binsum[NB1];
    __shared__ unsigned int s_cnt;
    __shared__ unsigned int w_pc[BLK / 32];
    __shared__ float        w_ps[BLK / 32];

    const int tid  = threadIdx.x;
    const int lane = tid & 31;

#pragma unroll
    for (int w = 0; w < 8; w++) sh[w * BLK + tid] = 0u;
    if (tid < NB1) s_binsum[tid] = 0u;
    if (tid == 0) s_cnt = 0u;
    __syncthreads();

    unsigned int posc = 0;
    float poss = 0.0f;
    const int n4   = n >> 2;
    const int step = gridDim.x * BLK;
    const long long rb = (long long)blockIdx.x * (long long)cap;

    // process one element; returns candidacy (negative with p >= 0.5)
    auto procE = [&](float p, float g, float mm, bool in) -> bool {
        bool valid = in && (mm > 0.5f);
        bool ispos = valid && (g > 0.5f);
        bool isneg = valid && !(g > 0.5f);
        if (ispos) { posc++; poss += pos_loss(p); }
        if (isneg) {
            int b = (int)(p * 32.0f);
            b = max(0, min(b, NB1 - 1));
            sh[(b >> 2) * BLK + tid] += 1u << ((b & 3) << 3);
        }
        return isneg && (p >= 0.5f);
    };

    // warp-aggregated append offset (requires full-warp convergence)
    auto warpOffset = [&](int cnt) -> unsigned {
        int incl = cnt;
#pragma unroll
        for (int o = 1; o < 32; o <<= 1) {
            int v = __shfl_up_sync(0xffffffffu, incl, o);
            if (lane >= o) incl += v;
        }
        unsigned total = (unsigned)__shfl_sync(0xffffffffu, incl, 31);
        unsigned base = 0;
        if (lane == 31 && total) base = atomicAdd(&s_cnt, total);
        base = __shfl_sync(0xffffffffu, base, 31);
        return base + (unsigned)(incl - cnt);
    };

    int ibase = blockIdx.x * BLK;
    // main loop: unroll x2 (6 independent LDG.128 per burst)
    while (ibase + step + BLK <= n4) {
        int i0 = ibase + tid, i1 = i0 + step;
        float4 pa = pred4[i0], ga = gt4[i0], ma = mask4[i0];
        float4 pb = pred4[i1], gb = gt4[i1], mb = mask4[i1];
        bool c0 = procE(pa.x, ga.x, ma.x, true);
        bool c1 = procE(pa.y, ga.y, ma.y, true);
        bool c2 = procE(pa.z, ga.z, ma.z, true);
        bool c3 = procE(pa.w, ga.w, ma.w, true);
        bool c4 = procE(pb.x, gb.x, mb.x, true);
        bool c5 = procE(pb.y, gb.y, mb.y, true);
        bool c6 = procE(pb.z, gb.z, mb.z, true);
        bool c7 = procE(pb.w, gb.w, mb.w, true);
        if (use_scr) {
            int cnt = (int)c0 + c1 + c2 + c3 + c4 + c5 + c6 + c7;
            unsigned o = warpOffset(cnt);
            if (c0) g_scr[rb + o++] = pa.x;
            if (c1) g_scr[rb + o++] = pa.y;
            if (c2) g_scr[rb + o++] = pa.z;
            if (c3) g_scr[rb + o++] = pa.w;
            if (c4) g_scr[rb + o++] = pb.x;
            if (c5) g_scr[rb + o++] = pb.y;
            if (c6) g_scr[rb + o++] = pb.z;
            if (c7) g_scr[rb + o++] = pb.w;
        }
        ibase += 2 * step;
    }
    // remainder: block-uniform trips, predicated loads
    for (; ibase < n4; ibase += step) {
        int i = ibase + tid;
        bool in = i < n4;
        float4 pa = in ? pred4[i] : make_float4(0.f, 0.f, 0.f, 0.f);
        float4 ga = in ? gt4[i]   : make_float4(1.f, 1.f, 1.f, 1.f);
        float4 ma = in ? mask4[i] : make_float4(0.f, 0.f, 0.f, 0.f);
        bool c0 = procE(pa.x, ga.x, ma.x, in);
        bool c1 = procE(pa.y, ga.y, ma.y, in);
        bool c2 = procE(pa.z, ga.z, ma.z, in);
        bool c3 = procE(pa.w, ga.w, ma.w, in);
        if (use_scr) {
            int cnt = (int)c0 + c1 + c2 + c3;
            unsigned o = warpOffset(cnt);
            if (c0) g_scr[rb + o++] = pa.x;
            if (c1) g_scr[rb + o++] = pa.y;
            if (c2) g_scr[rb + o++] = pa.z;
            if (c3) g_scr[rb + o++] = pa.w;
        }
    }
    // scalar tail (n % 4), block 0 only
    if (blockIdx.x == 0) {
        for (int i = (n4 << 2) + tid; i < n; i += BLK) {
            float p = pred[i], g = gt[i], mm = mask[i];
            bool valid = mm > 0.5f;
            bool ispos = valid && (g > 0.5f);
            bool isneg = valid && !(g > 0.5f);
            if (ispos) { posc++; poss += pos_loss(p); }
            if (isneg) {
                int b = (int)(p * 32.0f);
                b = max(0, min(b, NB1 - 1));
                sh[(b >> 2) * BLK + tid] += 1u << ((b & 3) << 3);
                if (use_scr && p >= 0.5f) {
                    unsigned o = atomicAdd(&s_cnt, 1u);
                    g_scr[rb + o] = p;
                }
            }
        }
    }
    __syncthreads();

    // flush per-thread u8 histogram columns (staggered, conflict-free)
    {
        const int b     = tid & 31;
        const int chunk = tid >> 5;        // 8 chunks of 32 columns
        const int w     = (b >> 2) * BLK;
        const int shft  = (b & 3) << 3;
        unsigned s = 0;
#pragma unroll
        for (int jj = 0; jj < 32; jj++) {
            int j = chunk * 32 + ((jj + b) & 31);
            s += (sh[w + j] >> shft) & 0xFFu;
        }
        if (s) atomicAdd(&s_binsum[b], s);
    }

#pragma unroll
    for (int o = 16; o > 0; o >>= 1) {
        posc += __shfl_down_sync(0xffffffffu, posc, o);
        poss += __shfl_down_sync(0xffffffffu, poss, o);
    }
    if (lane == 0) { w_pc[tid >> 5] = posc; w_ps[tid >> 5] = poss; }
    __syncthreads();

    if (tid < NB1 && s_binsum[tid]) atomicAdd(&g_h1[tid], s_binsum[tid]);
    if (tid == 0) {
        unsigned pc = 0; float ps = 0.0f;
#pragma unroll
        for (int w = 0; w < BLK / 32; w++) { pc += w_pc[w]; ps += w_ps[w]; }
        if (pc) atomicAdd(&g_pos_cnt, pc);
        atomicAdd(&g_pos_sum, (double)ps);
        g_cnt_blk[blockIdx.x] = s_cnt;
    }
}

// ---------------------------------------------------------------------------
// K2
// ---------------------------------------------------------------------------
__global__ void __launch_bounds__(BLK) k2_refine(
    const float4* __restrict__ pred4, const float4* __restrict__ gt4,
    const float4* __restrict__ mask4,
    const float* __restrict__ pred, const float* __restrict__ gt,
    const float* __restrict__ mask, int n, int cap, int use_scr)
{
    __shared__ int          s_T1;
    __shared__ unsigned int s_h1[NB1];
    __shared__ unsigned int s_c2[NB2];
    __shared__ float        s_s2[NB2];
    __shared__ float        w_as[BLK / 32];

    const int tid = threadIdx.x;
    if (tid < NB1) s_h1[tid] = g_h1[tid];
    if (tid < NB2) { s_c2[tid] = 0u; s_s2[tid] = 0.0f; }
    __syncthreads();

    if (tid == 0) {
        long long negtot = 0;
        for (int i = 0; i < NB1; i++) negtot += (long long)s_h1[i];
        unsigned pos = g_pos_cnt;
        long long k3p = 3LL * (long long)pos;
        long long k = (pos == 0u) ? 0LL : (negtot < k3p ? negtot : k3p);
        int T1 = 1000;
        if (k > 0) {
            long long c = 0;
            for (int i = NB1 - 1; i >= 0; i--) {
                c += (long long)s_h1[i];
                if (c >= k) { T1 = i; break; }
            }
        }
        s_T1 = T1;
    }
    __syncthreads();
    const int T1 = s_T1;

    float asum = 0.0f;
    if (T1 < NB1) {
        if (use_scr && T1 >= 16) {
            // fast path: read only this block's compacted candidates
            const long long rb = (long long)blockIdx.x * (long long)cap;
            const unsigned cnt = g_cnt_blk[blockIdx.x];
            for (unsigned j = tid; j < cnt; j += BLK) {
                float p = g_scr[rb + j];
                int b = (int)(p * 32.0f);
                b = max(0, min(b, NB1 - 1));
                if (b > T1) {
                    asum += neg_loss(p);
                } else if (b == T1) {
                    int b2 = (int)(p * 2048.0f) - T1 * 64;
                    b2 = max(0, min(b2, NB2 - 1));
                    atomicAdd(&s_c2[b2], 1u);
                    atomicAdd(&s_s2[b2], neg_loss(p));
                }
            }
        } else {
            // fallback: full re-read of this block's strided range
            const int n4 = n >> 2;
            const int step = gridDim.x * BLK;
            for (int ib = blockIdx.x * BLK; ib < n4; ib += step) {
                int i = ib + tid;
                if (i < n4) {
                    float4 p = pred4[i], g = gt4[i], m = mask4[i];
                    float ps_[4] = {p.x, p.y, p.z, p.w};
                    float gs_[4] = {g.x, g.y, g.z, g.w};
                    float ms_[4] = {m.x, m.y, m.z, m.w};
#pragma unroll
                    for (int c = 0; c < 4; c++) {
                        if (ms_[c] > 0.5f && gs_[c] < 0.5f) {
                            int b = (int)(ps_[c] * 32.0f);
                            b = max(0, min(b, NB1 - 1));
                            if (b > T1) asum += neg_loss(ps_[c]);
                            else if (b == T1) {
                                int b2 = (int)(ps_[c] * 2048.0f) - T1 * 64;
                                b2 = max(0, min(b2, NB2 - 1));
                                atomicAdd(&s_c2[b2], 1u);
                                atomicAdd(&s_s2[b2], neg_loss(ps_[c]));
                            }
                        }
                    }
                }
            }
            if (blockIdx.x == 0) {
                for (int i = (n4 << 2) + tid; i < n; i += BLK) {
                    float p = pred[i], g = gt[i], mm = mask[i];
                    if (mm > 0.5f && g < 0.5f) {
                        int b = (int)(p * 32.0f);
                        b = max(0, min(b, NB1 - 1));
                        if (b > T1) asum += neg_loss(p);
                        else if (b == T1) {
                            int b2 = (int)(p * 2048.0f) - T1 * 64;
                            b2 = max(0, min(b2, NB2 - 1));
                            atomicAdd(&s_c2[b2], 1u);
                            atomicAdd(&s_s2[b2], neg_loss(p));
                        }
                    }
                }
            }
        }
    }

#pragma unroll
    for (int o = 16; o > 0; o >>= 1)
        asum += __shfl_down_sync(0xffffffffu, asum, o);
    if ((tid & 31) == 0) w_as[tid >> 5] = asum;
    __syncthreads();

    if (tid < NB2 && s_c2[tid]) {
        atomicAdd(&g_h2c[tid], s_c2[tid]);
        atomicAdd(&g_h2s[tid], s_s2[tid]);
    }
    if (tid == 0) {
        float as = 0.0f;
#pragma unroll
        for (int w = 0; w < BLK / 32; w++) as += w_as[w];
        atomicAdd(&g_above_sum, (double)as);
    }
}

// ---------------------------------------------------------------------------
// K3: finalize + reset globals for graph replay
// ---------------------------------------------------------------------------
__global__ void k3_finalize(float* __restrict__ out)
{
    const int tid = threadIdx.x;
    if (tid == 0) {
        long long negtot = 0;
        for (int i = 0; i < NB1; i++) negtot += (long long)g_h1[i];
        unsigned pos = g_pos_cnt;
        long long k3p = 3LL * (long long)pos;
        long long k = (pos == 0u) ? 0LL : (negtot < k3p ? negtot : k3p);

        double nsum = 0.0;
        if (k > 0) {
            long long c = 0, cAbove1 = 0;
            for (int i = NB1 - 1; i >= 0; i--) {
                long long cn = c + (long long)g_h1[i];
                if (cn >= k) { cAbove1 = c; break; }
                c = cn;
            }
            long long r = k - cAbove1;

            long long c2 = 0, cAbove2 = 0;
            double s2above = 0.0;
            int T2 = -1;
            for (int i = NB2 - 1; i >= 0; i--) {
                long long cn = c2 + (long long)g_h2c[i];
                if (cn >= r) { T2 = i; cAbove2 = c2; break; }
                s2above += (double)g_h2s[i];
                c2 = cn;
            }
            double part = 0.0;
            if (T2 >= 0 && g_h2c[T2] > 0u) {
                long long r2 = r - cAbove2;
                if (r2 < 0) r2 = 0;
                part = (double)g_h2s[T2] * ((double)r2 / (double)g_h2c[T2]);
            }
            nsum = g_above_sum + s2above + part;
        }

        double denom = (double)pos + (double)k + 1e-6;
        out[0] = (float)((g_pos_sum + nsum) / denom);
    }
    __syncthreads();

    if (tid < NB1) g_h1[tid] = 0u;
    for (int i = tid; i < NB2; i += blockDim.x) { g_h2c[i] = 0u; g_h2s[i] = 0.0f; }
    if (tid == 0) {
        g_pos_cnt   = 0u;
        g_pos_sum   = 0.0;
        g_above_sum = 0.0;
    }
}

// ---------------------------------------------------------------------------
extern "C" void kernel_launch(void* const* d_in, const int* in_sizes, int n_in,
                              void* d_out, int out_size)
{
    const float* pred = (const float*)d_in[0];
    const float* gt   = (const float*)d_in[1];
    const float* mask = (const float*)d_in[2];
    float* out = (float*)d_out;
    const int n = in_sizes[0];

    const float4* pred4 = (const float4*)pred;
    const float4* gt4   = (const float4*)gt;
    const float4* mask4 = (const float4*)mask;

    int n4 = n >> 2;
    int grid = (n4 + BLK - 1) / BLK;
    if (grid > GRID_CAP) grid = GRID_CAP;
    if (grid < 1) grid = 1;

    int iters = (n4 + grid * BLK - 1) / (grid * BLK);
    long long cap = (long long)iters * BLK * 4 + 8;
    int use_scr = ((long long)grid * cap <= (long long)SCR_SZ) ? 1 : 0;

    k1_hist  <<<grid, BLK>>>(pred4, gt4, mask4, pred, gt, mask, n, (int)cap, use_scr);
    k2_refine<<<grid, BLK>>>(pred4, gt4, mask4, pred, gt, mask, n, (int)cap, use_scr);
    k3_finalize<<<1, 128>>>(out);
}